// round 9
// baseline (speedup 1.0000x reference)
#include <cuda_runtime.h>
#include <math.h>
#include <stdint.h>

#define LSEQ 1026
#define BB   2
#define BLT  (BB*LSEQ)   // 2052
#define DMO  256
#define EDI  512
#define ED2  1024
#define NS   16
#define RRW  16
#define DBCW 48
#define NBR  4
#define NCHK 18
#define CLEN 57          // 18*57 = 1026
#define EQ   128

// ------------------------- scratch (device globals; no allocs) -------------
__device__ float g_xz[(size_t)BLT*ED2];
__device__ float g_dbc[NBR][(size_t)BLT*DBCW];
__device__ float g_sum[(size_t)NBR*BB*NCHK*32*EDI];
__device__ float g_h0[(size_t)NBR*BB*NCHK*NS*EDI];
__device__ float g_g[NBR][(size_t)BLT*EDI];
__device__ float g_y[(size_t)BLT*EDI];

struct BranchPtrs { const float *cw,*cb,*xpw,*dtw,*dtb,*Al,*Dp; };
struct AllPtrs { BranchPtrs br[NBR]; };

// ------------------------- index maps ---------------------------------------
__device__ __forceinline__ int pi_map(int p) {
    if (p == 0 || p == LSEQ - 1) return p;
    int q = p - 1;
    int i = q >> 5, j = q & 31;
    return (j << 5) + i + 1;
}
__device__ __forceinline__ int in_row(int s, int p) {
    if (s == 0) return p;
    if (s == 1) return LSEQ - 1 - p;
    if (s == 2) return pi_map(p);
    return pi_map(LSEQ - 1 - p);
}

// ------------------------- tf32 helpers --------------------------------------
__device__ __forceinline__ void split1(float x, float& hi, float& lo) {
    uint32_t u;
    asm("cvt.rna.tf32.f32 %0, %1;" : "=r"(u) : "f"(x));
    hi = __uint_as_float(u);
    float r = x - hi;
    asm("cvt.rna.tf32.f32 %0, %1;" : "=r"(u) : "f"(r));
    lo = __uint_as_float(u);
}
__device__ __forceinline__ void mma_tf32(float c[4], const uint32_t a[4],
                                         uint32_t b0, uint32_t b1) {
    asm volatile("mma.sync.aligned.m16n8k8.row.col.f32.tf32.tf32.f32 "
        "{%0,%1,%2,%3}, {%4,%5,%6,%7}, {%8,%9}, {%0,%1,%2,%3};"
        : "+f"(c[0]), "+f"(c[1]), "+f"(c[2]), "+f"(c[3])
        : "r"(a[0]), "r"(a[1]), "r"(a[2]), "r"(a[3]), "r"(b0), "r"(b1));
}
#define ST4S(TH, TL, K0, R, V) { \
    float h_, l_; \
    split1((V).x, h_, l_); TH[(K0)+0][R]=h_; TL[(K0)+0][R]=l_; \
    split1((V).y, h_, l_); TH[(K0)+1][R]=h_; TL[(K0)+1][R]=l_; \
    split1((V).z, h_, l_); TH[(K0)+2][R]=h_; TL[(K0)+2][R]=l_; \
    split1((V).w, h_, l_); TH[(K0)+3][R]=h_; TL[(K0)+3][R]=l_; }

// ====== in-GEMM (3xtf32): xz = x @ in_w^T. 128x64 tile, K=256 ==============
__global__ __launch_bounds__(256)
void in_gemm_mma(const float* __restrict__ A, const float* __restrict__ Bm,
                 float* __restrict__ C) {
    extern __shared__ float sh[];
    float (*Ah)[136] = (float(*)[136])sh;
    float (*Alo)[136] = (float(*)[136])(sh + 32*136);
    float (*Bh)[72]  = (float(*)[72])(sh + 2*32*136);
    float (*Blo)[72] = (float(*)[72])(sh + 2*32*136 + 32*72);
    int tid = threadIdx.x;
    int n0 = blockIdx.x * 64, m0 = blockIdx.y * 128;
    int ra = tid >> 1, ka = (tid & 1) * 16;
    bool mok = (m0 + ra) < BLT;
    const float* Ap = A + (size_t)(m0 + ra) * DMO + ka;
    int rb = tid >> 2, kb = (tid & 3) * 8;
    const float* Bp = Bm + (size_t)(n0 + rb) * DMO + kb;
    int lane = tid & 31, wid = tid >> 5;
    int g = lane >> 2, t4 = lane & 3;
    int wm = (wid & 3) * 32, wn = (wid >> 2) * 32;

    float4 a[4], b[2];
#pragma unroll
    for (int i = 0; i < 4; i++)
        a[i] = mok ? *(const float4*)(Ap + 4*i) : make_float4(0,0,0,0);
    b[0] = *(const float4*)Bp; b[1] = *(const float4*)(Bp + 4);

    float acc[2][4][4];
#pragma unroll
    for (int mi = 0; mi < 2; mi++)
#pragma unroll
        for (int ni = 0; ni < 4; ni++)
#pragma unroll
            for (int q = 0; q < 4; q++) acc[mi][ni][q] = 0.f;

#pragma unroll 1
    for (int s = 0; s < 8; s++) {
#pragma unroll
        for (int i = 0; i < 4; i++) { ST4S(Ah, Alo, ka + 4*i, ra, a[i]); }
        ST4S(Bh, Blo, kb, rb, b[0]); ST4S(Bh, Blo, kb + 4, rb, b[1]);
        __syncthreads();
        if (s + 1 < 8) {
            int off = 32 * (s + 1);
#pragma unroll
            for (int i = 0; i < 4; i++)
                a[i] = mok ? *(const float4*)(Ap + off + 4*i) : make_float4(0,0,0,0);
            b[0] = *(const float4*)(Bp + off); b[1] = *(const float4*)(Bp + off + 4);
        }
#pragma unroll
        for (int k8 = 0; k8 < 4; k8++) {
            int kr = k8 * 8 + t4;
            uint32_t ah[2][4], al[2][4];
#pragma unroll
            for (int mi = 0; mi < 2; mi++) {
                int mb = wm + mi * 16 + g;
                ah[mi][0] = __float_as_uint(Ah[kr][mb]);
                ah[mi][1] = __float_as_uint(Ah[kr][mb + 8]);
                ah[mi][2] = __float_as_uint(Ah[kr + 4][mb]);
                ah[mi][3] = __float_as_uint(Ah[kr + 4][mb + 8]);
                al[mi][0] = __float_as_uint(Alo[kr][mb]);
                al[mi][1] = __float_as_uint(Alo[kr][mb + 8]);
                al[mi][2] = __float_as_uint(Alo[kr + 4][mb]);
                al[mi][3] = __float_as_uint(Alo[kr + 4][mb + 8]);
            }
#pragma unroll
            for (int ni = 0; ni < 4; ni++) {
                int nb = wn + ni * 8 + g;
                uint32_t b0h = __float_as_uint(Bh[kr][nb]);
                uint32_t b1h = __float_as_uint(Bh[kr + 4][nb]);
                uint32_t b0l = __float_as_uint(Blo[kr][nb]);
                uint32_t b1l = __float_as_uint(Blo[kr + 4][nb]);
#pragma unroll
                for (int mi = 0; mi < 2; mi++) {
                    mma_tf32(acc[mi][ni], al[mi], b0h, b1h);
                    mma_tf32(acc[mi][ni], ah[mi], b0l, b1l);
                    mma_tf32(acc[mi][ni], ah[mi], b0h, b1h);
                }
            }
        }
        __syncthreads();
    }
#pragma unroll
    for (int mi = 0; mi < 2; mi++)
#pragma unroll
        for (int ni = 0; ni < 4; ni++) {
            int row = m0 + wm + mi * 16 + g;
            int col = n0 + wn + ni * 8 + 2 * t4;
            if (row < BLT)
                *(float2*)&C[(size_t)row * ED2 + col] =
                    make_float2(acc[mi][ni][0], acc[mi][ni][1]);
            if (row + 8 < BLT)
                *(float2*)&C[(size_t)(row + 8) * ED2 + col] =
                    make_float2(acc[mi][ni][2], acc[mi][ni][3]);
        }
}

// ====== dBC (3xtf32) with FUSED depthwise conv + SiLU on A operand ==========
// 64x48 tile, K=512, 256 thr, 8 warps (4m x 2n). A = silu(conv(xz)) on the fly.
__global__ __launch_bounds__(256)
void dbc_conv_mma(AllPtrs P) {
    extern __shared__ float sh[];
    float* cwS = sh;                                    // 2048
    float* cbS = sh + 2048;                             // 512
    float (*Ah)[72]  = (float(*)[72])(sh + 2560);       // 2304
    float (*Alo)[72] = (float(*)[72])(sh + 4864);       // 2304
    float (*Bh)[56]  = (float(*)[56])(sh + 7168);       // 1792
    float (*Blo)[56] = (float(*)[56])(sh + 8960);       // 1792
    float* raw = sh + 10752;                            // 68*35 = 2380
    int* srcS = (int*)(sh + 13132);                     // 68

    int tid = threadIdx.x;
    int s = blockIdx.x;
    int m0 = blockIdx.y * 64;
    float* C = g_dbc[s];

    // stage weights once
    const float* cw = P.br[s].cw;
    for (int i = tid; i < 2048; i += 256) cwS[i] = cw[i];
    const float* cbp = P.br[s].cb;
    for (int i = tid; i < 512; i += 256) cbS[i] = cbp[i];
    // source-row map for the 67-row conv window
    if (tid < 68) {
        int gg = m0 - 3 + tid;
        int sr = -1;
        if (gg >= 0 && gg < BLT) {
            int bb = gg / LSEQ, lg = gg % LSEQ;
            sr = bb * LSEQ + in_row(s, lg);
        }
        srcS[tid] = sr;
    }
    __syncthreads();

    int r = tid >> 2, cgrp = tid & 3;     // conv: output row r, channels cgrp*8..+8
    int l_m = (m0 + r) % LSEQ;
    bool bok = tid < 192;
    int rb = tid >> 2, kb = (tid & 3) * 8;
    const float* Bm = P.br[s].xpw;
    const float* Bbase = Bm + (size_t)rb * EDI + kb;

    int lane = tid & 31, wid = tid >> 5;
    int g = lane >> 2, t4 = lane & 3;
    int wm = (wid & 3) * 16, wn = (wid >> 2) * 24;

    // prefetch stage 0
    float4 rr[3], b0, b1;
    {
        int ch0 = 0;
#pragma unroll
        for (int u = 0; u < 3; u++) {
            int idx = tid + 256 * u;
            rr[u] = make_float4(0,0,0,0);
            if (idx < 536) {
                int j = idx >> 3, q = idx & 7;
                int sr = srcS[j];
                if (sr >= 0) rr[u] = *(const float4*)(g_xz + (size_t)sr * ED2 + ch0 + q * 4);
            }
        }
        b0 = bok ? *(const float4*)(Bbase + ch0) : make_float4(0,0,0,0);
        b1 = bok ? *(const float4*)(Bbase + ch0 + 4) : make_float4(0,0,0,0);
    }

    float acc[3][4];
#pragma unroll
    for (int ni = 0; ni < 3; ni++)
#pragma unroll
        for (int q = 0; q < 4; q++) acc[ni][q] = 0.f;

#pragma unroll 1
    for (int st = 0; st < 16; st++) {
        // stage stores: raw xz tile + B split
#pragma unroll
        for (int u = 0; u < 3; u++) {
            int idx = tid + 256 * u;
            if (idx < 536) {
                int j = idx >> 3, q = idx & 7;
                float* p = raw + j * 35 + q * 4;
                p[0] = rr[u].x; p[1] = rr[u].y; p[2] = rr[u].z; p[3] = rr[u].w;
            }
        }
        if (bok) { ST4S(Bh, Blo, kb, rb, b0); ST4S(Bh, Blo, kb + 4, rb, b1); }
        __syncthreads();

        // conv + SiLU + split into A tiles
        int ch0 = st * 32;
#pragma unroll
        for (int i = 0; i < 8; i++) {
            int c = cgrp * 8 + i;
            int e = ch0 + c;
            float4 w4 = *(const float4*)&cwS[e * 4];
            float t0 = raw[(r + 0) * 35 + c];
            float t1 = raw[(r + 1) * 35 + c];
            float t2 = raw[(r + 2) * 35 + c];
            float t3 = raw[(r + 3) * 35 + c];
            if (l_m < 3) t0 = 0.f;
            if (l_m < 2) t1 = 0.f;
            if (l_m < 1) t2 = 0.f;
            float u = cbS[e];
            u = fmaf(w4.x, t0, u); u = fmaf(w4.y, t1, u);
            u = fmaf(w4.z, t2, u); u = fmaf(w4.w, t3, u);
            float sg = 1.f / (1.f + __expf(-u));
            float xv = u * sg;
            float hi, lo; split1(xv, hi, lo);
            Ah[c][r] = hi; Alo[c][r] = lo;
        }
        __syncthreads();

        // prefetch next stage
        if (st + 1 < 16) {
            int ch0n = (st + 1) * 32;
#pragma unroll
            for (int u = 0; u < 3; u++) {
                int idx = tid + 256 * u;
                rr[u] = make_float4(0,0,0,0);
                if (idx < 536) {
                    int j = idx >> 3, q = idx & 7;
                    int sr = srcS[j];
                    if (sr >= 0) rr[u] = *(const float4*)(g_xz + (size_t)sr * ED2 + ch0n + q * 4);
                }
            }
            b0 = bok ? *(const float4*)(Bbase + ch0n) : make_float4(0,0,0,0);
            b1 = bok ? *(const float4*)(Bbase + ch0n + 4) : make_float4(0,0,0,0);
        }

        // mma
#pragma unroll
        for (int k8 = 0; k8 < 4; k8++) {
            int kr = k8 * 8 + t4;
            int mb = wm + g;
            uint32_t ah[4], al[4];
            ah[0] = __float_as_uint(Ah[kr][mb]);
            ah[1] = __float_as_uint(Ah[kr][mb + 8]);
            ah[2] = __float_as_uint(Ah[kr + 4][mb]);
            ah[3] = __float_as_uint(Ah[kr + 4][mb + 8]);
            al[0] = __float_as_uint(Alo[kr][mb]);
            al[1] = __float_as_uint(Alo[kr][mb + 8]);
            al[2] = __float_as_uint(Alo[kr + 4][mb]);
            al[3] = __float_as_uint(Alo[kr + 4][mb + 8]);
#pragma unroll
            for (int ni = 0; ni < 3; ni++) {
                int nb = wn + ni * 8 + g;
                uint32_t b0h = __float_as_uint(Bh[kr][nb]);
                uint32_t b1h = __float_as_uint(Bh[kr + 4][nb]);
                uint32_t b0l = __float_as_uint(Blo[kr][nb]);
                uint32_t b1l = __float_as_uint(Blo[kr + 4][nb]);
                mma_tf32(acc[ni], al, b0h, b1h);
                mma_tf32(acc[ni], ah, b0l, b1l);
                mma_tf32(acc[ni], ah, b0h, b1h);
            }
        }
        __syncthreads();
    }
#pragma unroll
    for (int ni = 0; ni < 3; ni++) {
        int row = m0 + wm + g;
        int col = wn + ni * 8 + 2 * t4;
        if (row < BLT)
            *(float2*)&C[(size_t)row * DBCW + col] = make_float2(acc[ni][0], acc[ni][1]);
        if (row + 8 < BLT)
            *(float2*)&C[(size_t)(row + 8) * DBCW + col] = make_float2(acc[ni][2], acc[ni][3]);
    }
}

// ---------- combine: y = 0.25 * (g0 + rev(g1) + cross(g2) + revcross(g3)) ---
__global__ __launch_bounds__(512)
void combine_k() {
    int bl = blockIdx.x;
    int b = bl / LSEQ, l = bl % LSEQ;
    int e = threadIdx.x;
    size_t r1 = (size_t)(b * LSEQ + (LSEQ - 1 - l)) * EDI;
    size_t r2 = (size_t)(b * LSEQ + pi_map(l)) * EDI;
    size_t r3 = (size_t)(b * LSEQ + pi_map(LSEQ - 1 - l)) * EDI;
    g_y[(size_t)bl * EDI + e] = 0.25f * (g_g[0][(size_t)bl * EDI + e]
                                       + g_g[1][r1 + e]
                                       + g_g[2][r2 + e]
                                       + g_g[3][r3 + e]);
}

// ====== out-GEMM (3xtf32): y @ out_w^T. 64x64 tile, K=512, 256 thr ==========
__global__ __launch_bounds__(256)
void out_gemm_mma(const float* __restrict__ out_w, float* __restrict__ C) {
    __shared__ float Ah[32][72], Alo[32][72];
    __shared__ float Bh[32][72], Blo[32][72];
    int tid = threadIdx.x;
    int n0 = blockIdx.x * 64, m0 = blockIdx.y * 64;
    int ra = tid >> 2, ka = (tid & 3) * 8;
    bool mok = (m0 + ra) < BLT;
    const float* Ap = g_y + (size_t)(m0 + ra) * EDI + ka;
    const float* Bp = out_w + (size_t)(n0 + ra) * EDI + ka;
    int lane = tid & 31, wid = tid >> 5;
    int g = lane >> 2, t4 = lane & 3;
    int wm = (wid & 3) * 16, wn = (wid >> 2) * 32;

    float4 a[2], b[2];
    a[0] = mok ? *(const float4*)Ap : make_float4(0,0,0,0);
    a[1] = mok ? *(const float4*)(Ap + 4) : make_float4(0,0,0,0);
    b[0] = *(const float4*)Bp; b[1] = *(const float4*)(Bp + 4);

    float acc[4][4];
#pragma unroll
    for (int ni = 0; ni < 4; ni++)
#pragma unroll
        for (int q = 0; q < 4; q++) acc[ni][q] = 0.f;

#pragma unroll 1
    for (int s2 = 0; s2 < 16; s2++) {
        ST4S(Ah, Alo, ka, ra, a[0]); ST4S(Ah, Alo, ka + 4, ra, a[1]);
        ST4S(Bh, Blo, ka, ra, b[0]); ST4S(Bh, Blo, ka + 4, ra, b[1]);
        __syncthreads();
        if (s2 + 1 < 16) {
            int off = 32 * (s2 + 1);
            a[0] = mok ? *(const float4*)(Ap + off) : make_float4(0,0,0,0);
            a[1] = mok ? *(const float4*)(Ap + off + 4) : make_float4(0,0,0,0);
            b[0] = *(const float4*)(Bp + off); b[1] = *(const float4*)(Bp + off + 4);
        }
#pragma unroll
        for (int k8 = 0; k8 < 4; k8++) {
            int kr = k8 * 8 + t4;
            int mb = wm + g;
            uint32_t ah[4], al[4];
            ah[0] = __float_as_uint(Ah[kr][mb]);
            ah[1] = __float_as_uint(Ah[kr][mb + 8]);
            ah[2] = __float_as_uint(Ah[kr + 4][mb]);
            ah[3] = __float_as_uint(Ah[kr + 4][mb + 8]);
            al[0] = __float_as_uint(Alo[kr][mb]);
            al[1] = __float_as_uint(Alo[kr][mb + 8]);
            al[2] = __float_as_uint(Alo[kr + 4][mb]);
            al[3] = __float_as_uint(Alo[kr + 4][mb + 8]);
#pragma unroll
            for (int ni = 0; ni < 4; ni++) {
                int nb = wn + ni * 8 + g;
                uint32_t b0h = __float_as_uint(Bh[kr][nb]);
                uint32_t b1h = __float_as_uint(Bh[kr + 4][nb]);
                uint32_t b0l = __float_as_uint(Blo[kr][nb]);
                uint32_t b1l = __float_as_uint(Blo[kr + 4][nb]);
                mma_tf32(acc[ni], al, b0h, b1h);
                mma_tf32(acc[ni], ah, b0l, b1l);
                mma_tf32(acc[ni], ah, b0h, b1h);
            }
        }
        __syncthreads();
    }
#pragma unroll
    for (int ni = 0; ni < 4; ni++) {
        int row = m0 + wm + g;
        int col = n0 + wn + ni * 8 + 2 * t4;
        if (row < BLT)
            *(float2*)&C[(size_t)row * DMO + col] = make_float2(acc[ni][0], acc[ni][1]);
        if (row + 8 < BLT)
            *(float2*)&C[(size_t)(row + 8) * DMO + col] = make_float2(acc[ni][2], acc[ni][3]);
    }
}

// -------- scan phase 1: conv + delta fused, channel-quarter -----------------
__global__ __launch_bounds__(128)
void scan1(AllPtrs P) {
    __shared__ float dtw_s[EQ * 17];
    __shared__ float f_s[CLEN][NS];
    __shared__ float Bsm[CLEN * NS];
    int blk = blockIdx.x;
    int quarter = blk & 3;
    int blk2 = blk >> 2;
    int s = blk2 / (BB * NCHK);
    int rem = blk2 % (BB * NCHK);
    int b = rem / NCHK, c = rem % NCHK;
    int e0 = quarter * EQ;
    int e = e0 + threadIdx.x;
    const float* dtw = P.br[s].dtw;
    for (int idx = threadIdx.x; idx < EQ * RRW; idx += blockDim.x)
        dtw_s[(idx >> 4) * 17 + (idx & 15)] = dtw[e0 * RRW + idx];
    for (int idx = threadIdx.x; idx < CLEN * 32; idx += blockDim.x) {
        int t = idx >> 5, q = idx & 31;
        float v = g_dbc[s][(size_t)(b * LSEQ + c * CLEN + t) * DBCW + q];
        if (q < 16) f_s[t][q] = v;
        else        Bsm[t * NS + (q - 16)] = v;
    }
    __syncthreads();
    float w[RRW];
#pragma unroll
    for (int q = 0; q < RRW; q++) w[q] = dtw_s[threadIdx.x * 17 + q];
    float dtb = P.br[s].dtb[e];
    // inline fast-structure detection + A values
    const float* Al = P.br[s].Al;
    float A_[NS];
    bool fastb = true;
#pragma unroll
    for (int n = 0; n < NS; n++) {
        float av = -__expf(Al[e * NS + n]);
        A_[n] = av;
        if (fabsf(av + (float)(n + 1)) > 1e-4f * (float)(n + 1)) fastb = false;
    }
    // conv weights
    float4 cw4 = *(const float4*)(P.br[s].cw + e * 4);
    float cbv = P.br[s].cb[e];
    int l0 = c * CLEN;
    size_t bbase = (size_t)(b * LSEQ);
    float v0 = 0.f, v1 = 0.f, v2 = 0.f;
    if (l0 >= 3) v0 = g_xz[(bbase + in_row(s, l0 - 3)) * ED2 + e];
    if (l0 >= 2) v1 = g_xz[(bbase + in_row(s, l0 - 2)) * ED2 + e];
    if (l0 >= 1) v2 = g_xz[(bbase + in_row(s, l0 - 1)) * ED2 + e];
    float v3 = g_xz[(bbase + in_row(s, l0)) * ED2 + e];

    float h[NS], Pn[NS];
#pragma unroll
    for (int n = 0; n < NS; n++) { h[n] = 0.f; Pn[n] = 1.f; }
    float Rp = 1.f;
    for (int t = 0; t < CLEN; t++) {
        float v3n = 0.f;
        if (t + 1 < CLEN) v3n = g_xz[(bbase + in_row(s, l0 + t + 1)) * ED2 + e];
        float uc = cbv;
        uc = fmaf(cw4.x, v0, uc); uc = fmaf(cw4.y, v1, uc);
        uc = fmaf(cw4.z, v2, uc); uc = fmaf(cw4.w, v3, uc);
        float sgc = 1.f / (1.f + __expf(-uc));
        float x_cur = uc * sgc;
        float u = dtb;
#pragma unroll
        for (int q = 0; q < RRW; q++) u = fmaf(f_s[t][q], w[q], u);
        float d = fmaxf(u, 0.f) + log1pf(__expf(-fabsf(u)));
        float dx = d * x_cur;
        if (fastb) {
            float r = __expf(-d);
            Rp *= r;
            float dA = 1.f;
#pragma unroll
            for (int n = 0; n < NS; n++) {
                dA *= r;
                h[n] = fmaf(dA, h[n], dx * Bsm[t * NS + n]);
            }
        } else {
#pragma unroll
            for (int n = 0; n < NS; n++) {
                float dA = __expf(d * A_[n]);
                Pn[n] *= dA;
                h[n] = fmaf(dA, h[n], dx * Bsm[t * NS + n]);
            }
        }
        v0 = v1; v1 = v2; v2 = v3; v3 = v3n;
    }
    if (fastb) {
        float q = 1.f;
#pragma unroll
        for (int n = 0; n < NS; n++) { q *= Rp; Pn[n] = q; }
    }
    size_t base = (size_t)((s * BB + b) * NCHK + c) * 32 * EDI + e;
#pragma unroll
    for (int n = 0; n < NS; n++) g_sum[base + (size_t)n * EDI] = h[n];
#pragma unroll
    for (int n = 0; n < NS; n++) g_sum[base + (size_t)(16 + n) * EDI] = Pn[n];
}

// ---------- scan phase 2: chunk combine, parallel over (s,b,n) --------------
__global__ __launch_bounds__(512)
void scan2() {
    int n = blockIdx.x & 15;
    int sb = blockIdx.x >> 4;
    int e = threadIdx.x;
    float h = 0.f;
    for (int c = 0; c < NCHK; c++) {
        size_t idx = (size_t)(sb * NCHK + c);
        g_h0[idx * NS * EDI + (size_t)n * EDI + e] = h;
        size_t pb = idx * 32 * EDI + e;
        float hl = g_sum[pb + (size_t)n * EDI];
        float Pv = g_sum[pb + (size_t)(16 + n) * EDI];
        h = fmaf(Pv, h, hl);
    }
}

// -------- scan phase 3: conv + delta fused, full walk + gate ----------------
__global__ __launch_bounds__(128)
void scan3(AllPtrs P) {
    __shared__ float dtw_s[EQ * 17];
    __shared__ float f_s[CLEN][NS];
    __shared__ float Bsm[CLEN * NS];
    __shared__ float Csm[CLEN * NS];
    int blk = blockIdx.x;
    int quarter = blk & 3;
    int blk2 = blk >> 2;
    int s = blk2 / (BB * NCHK);
    int rem = blk2 % (BB * NCHK);
    int b = rem / NCHK, c = rem % NCHK;
    int e0 = quarter * EQ;
    int e = e0 + threadIdx.x;
    const float* dtw = P.br[s].dtw;
    for (int idx = threadIdx.x; idx < EQ * RRW; idx += blockDim.x)
        dtw_s[(idx >> 4) * 17 + (idx & 15)] = dtw[e0 * RRW + idx];
    for (int idx = threadIdx.x; idx < CLEN * DBCW; idx += blockDim.x) {
        int t = idx / DBCW, q = idx % DBCW;
        float v = g_dbc[s][(size_t)(b * LSEQ + c * CLEN + t) * DBCW + q];
        if (q < 16)      f_s[t][q] = v;
        else if (q < 32) Bsm[t * NS + (q - 16)] = v;
        else             Csm[t * NS + (q - 32)] = v;
    }
    __syncthreads();
    float w[RRW];
#pragma unroll
    for (int q = 0; q < RRW; q++) w[q] = dtw_s[threadIdx.x * 17 + q];
    float dtb = P.br[s].dtb[e];
    const float* Al = P.br[s].Al;
    float A_[NS];
    bool fastb = true;
#pragma unroll
    for (int n = 0; n < NS; n++) {
        float av = -__expf(Al[e * NS + n]);
        A_[n] = av;
        if (fabsf(av + (float)(n + 1)) > 1e-4f * (float)(n + 1)) fastb = false;
    }
    float Dv = P.br[s].Dp[e];
    float h[NS];
    {
        size_t sb = (size_t)((s * BB + b) * NCHK + c);
        size_t hb = sb * NS * EDI + e;
#pragma unroll
        for (int n = 0; n < NS; n++) h[n] = g_h0[hb + (size_t)n * EDI];
    }
    float4 cw4 = *(const float4*)(P.br[s].cw + e * 4);
    float cbv = P.br[s].cb[e];
    int l0 = c * CLEN;
    size_t bbase = (size_t)(b * LSEQ);
    float v0 = 0.f, v1 = 0.f, v2 = 0.f;
    if (l0 >= 3) v0 = g_xz[(bbase + in_row(s, l0 - 3)) * ED2 + e];
    if (l0 >= 2) v1 = g_xz[(bbase + in_row(s, l0 - 2)) * ED2 + e];
    if (l0 >= 1) v2 = g_xz[(bbase + in_row(s, l0 - 1)) * ED2 + e];
    size_t rp = (bbase + in_row(s, l0)) * ED2;
    float v3 = g_xz[rp + e];
    float za_cur = g_xz[rp + EDI + e];

    for (int t = 0; t < CLEN; t++) {
        int l = l0 + t;
        int bl = b * LSEQ + l;
        float v3n = 0.f, za_n = 0.f;
        if (t + 1 < CLEN) {
            size_t rpn = (bbase + in_row(s, l + 1)) * ED2;
            v3n = g_xz[rpn + e];
            za_n = g_xz[rpn + EDI + e];
        }
        float uc = cbv;
        uc = fmaf(cw4.x, v0, uc); uc = fmaf(cw4.y, v1, uc);
        uc = fmaf(cw4.z, v2, uc); uc = fmaf(cw4.w, v3, uc);
        float sgc = 1.f / (1.f + __expf(-uc));
        float x_cur = uc * sgc;
        float u = dtb;
#pragma unroll
        for (int q = 0; q < RRW; q++) u = fmaf(f_s[t][q], w[q], u);
        float d = fmaxf(u, 0.f) + log1pf(__expf(-fabsf(u)));
        float dx = d * x_cur;
        float acc = Dv * x_cur;
        if (fastb) {
            float r = __expf(-d);
            float dA = 1.f;
#pragma unroll
            for (int n = 0; n < NS; n++) {
                dA *= r;
                h[n] = fmaf(dA, h[n], dx * Bsm[t * NS + n]);
                acc = fmaf(h[n], Csm[t * NS + n], acc);
            }
        } else {
#pragma unroll
            for (int n = 0; n < NS; n++) {
                float dA = __expf(d * A_[n]);
                h[n] = fmaf(dA, h[n], dx * Bsm[t * NS + n]);
                acc = fmaf(h[n], Csm[t * NS + n], acc);
            }
        }
        float sz = za_cur / (1.f + __expf(-za_cur));
        g_g[s][(size_t)bl * EDI + e] = acc * sz;
        v0 = v1; v1 = v2; v2 = v3; v3 = v3n; za_cur = za_n;
    }
}

// ------------------------- launch ------------------------------------------
extern "C" void kernel_launch(void* const* d_in, const int* in_sizes, int n_in,
                              void* d_out, int out_size) {
    const float* x     = (const float*)d_in[0];
    const float* in_w  = (const float*)d_in[1];
    const float* out_w = (const float*)d_in[2];
    AllPtrs P;
    for (int s = 0; s < NBR; s++) {
        int o = 3 + 7 * s;
        P.br[s].cw  = (const float*)d_in[o + 0];
        P.br[s].cb  = (const float*)d_in[o + 1];
        P.br[s].xpw = (const float*)d_in[o + 2];
        P.br[s].dtw = (const float*)d_in[o + 3];
        P.br[s].dtb = (const float*)d_in[o + 4];
        P.br[s].Al  = (const float*)d_in[o + 5];
        P.br[s].Dp  = (const float*)d_in[o + 6];
    }
    float* p_xz;
    cudaGetSymbolAddress((void**)&p_xz, g_xz);

    const int IN_SMEM = (2*32*136 + 2*32*72) * 4;  // 53248
    const int DBC_SMEM = 13200 * 4;                // 52800
    cudaFuncSetAttribute(in_gemm_mma,  cudaFuncAttributeMaxDynamicSharedMemorySize, IN_SMEM);
    cudaFuncSetAttribute(dbc_conv_mma, cudaFuncAttributeMaxDynamicSharedMemorySize, DBC_SMEM);

    // xz = x @ in_w^T — 3xtf32, 272 blocks
    in_gemm_mma<<<dim3(ED2 / 64, (BLT + 127) / 128), 256, IN_SMEM>>>(x, in_w, p_xz);

    // dBC = silu(conv(xz)) @ xp_w^T — conv fused, 3xtf32, 132 blocks
    dbc_conv_mma<<<dim3(NBR, (BLT + 63) / 64), 256, DBC_SMEM>>>(P);

    // chunked selective scan (conv + delta fused) — 576 / 128 / 576 blocks
    scan1<<<NBR * BB * NCHK * 4, 128>>>(P);
    scan2<<<NBR * BB * NS, EDI>>>();
    scan3<<<NBR * BB * NCHK * 4, 128>>>(P);

    // combine permuted branch outputs — 2052 blocks
    combine_k<<<BLT, EDI>>>();

    // out = y @ out_w^T — 3xtf32, 132 blocks
    out_gemm_mma<<<dim3(DMO / 64, (BLT + 63) / 64), 256>>>(out_w, (float*)d_out);
}

// round 10
// speedup vs baseline: 1.1369x; 1.1369x over previous
#include <cuda_runtime.h>
#include <math.h>
#include <stdint.h>

#define LSEQ 1026
#define BB   2
#define BLT  (BB*LSEQ)   // 2052
#define DMO  256
#define EDI  512
#define ED2  1024
#define NS   16
#define RRW  16
#define DBCW 48
#define NBR  4
#define NCHK 18
#define CLEN 57          // 18*57 = 1026
#define EQ   128

// ------------------------- scratch (device globals; no allocs) -------------
__device__ float g_xz[(size_t)BLT*ED2];
__device__ float g_xa[NBR][(size_t)BLT*EDI];
__device__ float g_dbc[NBR][(size_t)BLT*DBCW];
__device__ float g_sum[(size_t)NBR*BB*NCHK*32*EDI];
__device__ float g_h0[(size_t)NBR*BB*NCHK*NS*EDI];
__device__ float g_g[NBR][(size_t)BLT*EDI];
__device__ float g_y[(size_t)BLT*EDI];
__device__ int   g_fast[NBR];

struct BranchPtrs { const float *cw,*cb,*xpw,*dtw,*dtb,*Al,*Dp; };
struct AllPtrs { BranchPtrs br[NBR]; };

// ------------------------- index maps ---------------------------------------
__device__ __forceinline__ int pi_map(int p) {
    if (p == 0 || p == LSEQ - 1) return p;
    int q = p - 1;
    int i = q >> 5, j = q & 31;
    return (j << 5) + i + 1;
}
__device__ __forceinline__ int in_row(int s, int p) {
    if (s == 0) return p;
    if (s == 1) return LSEQ - 1 - p;
    if (s == 2) return pi_map(p);
    return pi_map(LSEQ - 1 - p);
}

// ------------------------- tf32 helpers --------------------------------------
__device__ __forceinline__ void split1(float x, float& hi, float& lo) {
    uint32_t u;
    asm("cvt.rna.tf32.f32 %0, %1;" : "=r"(u) : "f"(x));
    hi = __uint_as_float(u);
    float r = x - hi;
    asm("cvt.rna.tf32.f32 %0, %1;" : "=r"(u) : "f"(r));
    lo = __uint_as_float(u);
}
__device__ __forceinline__ void mma_tf32(float c[4], const uint32_t a[4],
                                         uint32_t b0, uint32_t b1) {
    asm volatile("mma.sync.aligned.m16n8k8.row.col.f32.tf32.tf32.f32 "
        "{%0,%1,%2,%3}, {%4,%5,%6,%7}, {%8,%9}, {%0,%1,%2,%3};"
        : "+f"(c[0]), "+f"(c[1]), "+f"(c[2]), "+f"(c[3])
        : "r"(a[0]), "r"(a[1]), "r"(a[2]), "r"(a[3]), "r"(b0), "r"(b1));
}
#define ST4S(TH, TL, K0, R, V) { \
    float h_, l_; \
    split1((V).x, h_, l_); TH[(K0)+0][R]=h_; TL[(K0)+0][R]=l_; \
    split1((V).y, h_, l_); TH[(K0)+1][R]=h_; TL[(K0)+1][R]=l_; \
    split1((V).z, h_, l_); TH[(K0)+2][R]=h_; TL[(K0)+2][R]=l_; \
    split1((V).w, h_, l_); TH[(K0)+3][R]=h_; TL[(K0)+3][R]=l_; }

// ====== in-GEMM (3xtf32): xz = x @ in_w^T. 128x64 tile, K=256 ==============
__global__ __launch_bounds__(256)
void in_gemm_mma(const float* __restrict__ A, const float* __restrict__ Bm,
                 float* __restrict__ C) {
    extern __shared__ float sh[];
    float (*Ah)[136] = (float(*)[136])sh;
    float (*Alo)[136] = (float(*)[136])(sh + 32*136);
    float (*Bh)[72]  = (float(*)[72])(sh + 2*32*136);
    float (*Blo)[72] = (float(*)[72])(sh + 2*32*136 + 32*72);
    int tid = threadIdx.x;
    int n0 = blockIdx.x * 64, m0 = blockIdx.y * 128;
    int ra = tid >> 1, ka = (tid & 1) * 16;
    bool mok = (m0 + ra) < BLT;
    const float* Ap = A + (size_t)(m0 + ra) * DMO + ka;
    int rb = tid >> 2, kb = (tid & 3) * 8;
    const float* Bp = Bm + (size_t)(n0 + rb) * DMO + kb;
    int lane = tid & 31, wid = tid >> 5;
    int g = lane >> 2, t4 = lane & 3;
    int wm = (wid & 3) * 32, wn = (wid >> 2) * 32;

    float4 a[4], b[2];
#pragma unroll
    for (int i = 0; i < 4; i++)
        a[i] = mok ? *(const float4*)(Ap + 4*i) : make_float4(0,0,0,0);
    b[0] = *(const float4*)Bp; b[1] = *(const float4*)(Bp + 4);

    float acc[2][4][4];
#pragma unroll
    for (int mi = 0; mi < 2; mi++)
#pragma unroll
        for (int ni = 0; ni < 4; ni++)
#pragma unroll
            for (int q = 0; q < 4; q++) acc[mi][ni][q] = 0.f;

#pragma unroll 1
    for (int s = 0; s < 8; s++) {
#pragma unroll
        for (int i = 0; i < 4; i++) { ST4S(Ah, Alo, ka + 4*i, ra, a[i]); }
        ST4S(Bh, Blo, kb, rb, b[0]); ST4S(Bh, Blo, kb + 4, rb, b[1]);
        __syncthreads();
        if (s + 1 < 8) {
            int off = 32 * (s + 1);
#pragma unroll
            for (int i = 0; i < 4; i++)
                a[i] = mok ? *(const float4*)(Ap + off + 4*i) : make_float4(0,0,0,0);
            b[0] = *(const float4*)(Bp + off); b[1] = *(const float4*)(Bp + off + 4);
        }
#pragma unroll
        for (int k8 = 0; k8 < 4; k8++) {
            int kr = k8 * 8 + t4;
            uint32_t ah[2][4], al[2][4];
#pragma unroll
            for (int mi = 0; mi < 2; mi++) {
                int mb = wm + mi * 16 + g;
                ah[mi][0] = __float_as_uint(Ah[kr][mb]);
                ah[mi][1] = __float_as_uint(Ah[kr][mb + 8]);
                ah[mi][2] = __float_as_uint(Ah[kr + 4][mb]);
                ah[mi][3] = __float_as_uint(Ah[kr + 4][mb + 8]);
                al[mi][0] = __float_as_uint(Alo[kr][mb]);
                al[mi][1] = __float_as_uint(Alo[kr][mb + 8]);
                al[mi][2] = __float_as_uint(Alo[kr + 4][mb]);
                al[mi][3] = __float_as_uint(Alo[kr + 4][mb + 8]);
            }
#pragma unroll
            for (int ni = 0; ni < 4; ni++) {
                int nb = wn + ni * 8 + g;
                uint32_t b0h = __float_as_uint(Bh[kr][nb]);
                uint32_t b1h = __float_as_uint(Bh[kr + 4][nb]);
                uint32_t b0l = __float_as_uint(Blo[kr][nb]);
                uint32_t b1l = __float_as_uint(Blo[kr + 4][nb]);
#pragma unroll
                for (int mi = 0; mi < 2; mi++) {
                    mma_tf32(acc[mi][ni], al[mi], b0h, b1h);
                    mma_tf32(acc[mi][ni], ah[mi], b0l, b1l);
                    mma_tf32(acc[mi][ni], ah[mi], b0h, b1h);
                }
            }
        }
        __syncthreads();
    }
#pragma unroll
    for (int mi = 0; mi < 2; mi++)
#pragma unroll
        for (int ni = 0; ni < 4; ni++) {
            int row = m0 + wm + mi * 16 + g;
            int col = n0 + wn + ni * 8 + 2 * t4;
            if (row < BLT)
                *(float2*)&C[(size_t)row * ED2 + col] =
                    make_float2(acc[mi][ni][0], acc[mi][ni][1]);
            if (row + 8 < BLT)
                *(float2*)&C[(size_t)(row + 8) * ED2 + col] =
                    make_float2(acc[mi][ni][2], acc[mi][ni][3]);
        }
}

// ====== dBC (3xtf32): 64x48 tile, split-K(2), 256 thr, atomic epilogue ======
__global__ __launch_bounds__(256)
void dbc_mma(AllPtrs P) {
    __shared__ float Ah[32][72], Alo[32][72];
    __shared__ float Bh[32][56], Blo[32][56];
    int tid = threadIdx.x;
    int s = blockIdx.x;
    int m0 = blockIdx.y * 64;
    int kz = blockIdx.z;
    int kbase = kz * 256;
    const float* A  = g_xa[s];
    const float* Bm = P.br[s].xpw;
    float*       C  = g_dbc[s];
    int ra = tid >> 2, ka = (tid & 3) * 8;
    bool mok = (m0 + ra) < BLT;
    const float* Ap = A + (size_t)(m0 + ra) * EDI + kbase + ka;
    bool bok = tid < 192;
    int rb = tid >> 2;
    const float* Bp = Bm + (size_t)rb * EDI + kbase + ka;
    int lane = tid & 31, wid = tid >> 5;
    int g = lane >> 2, t4 = lane & 3;
    int wm = (wid & 3) * 16, wn = (wid >> 2) * 24;

    float4 a[2], b[2];
    a[0] = mok ? *(const float4*)Ap : make_float4(0,0,0,0);
    a[1] = mok ? *(const float4*)(Ap + 4) : make_float4(0,0,0,0);
    b[0] = bok ? *(const float4*)Bp : make_float4(0,0,0,0);
    b[1] = bok ? *(const float4*)(Bp + 4) : make_float4(0,0,0,0);

    float acc[3][4];
#pragma unroll
    for (int ni = 0; ni < 3; ni++)
#pragma unroll
        for (int q = 0; q < 4; q++) acc[ni][q] = 0.f;

#pragma unroll 1
    for (int s2 = 0; s2 < 8; s2++) {
        ST4S(Ah, Alo, ka, ra, a[0]); ST4S(Ah, Alo, ka + 4, ra, a[1]);
        if (bok) { ST4S(Bh, Blo, ka, rb, b[0]); ST4S(Bh, Blo, ka + 4, rb, b[1]); }
        __syncthreads();
        if (s2 + 1 < 8) {
            int off = 32 * (s2 + 1);
            a[0] = mok ? *(const float4*)(Ap + off) : make_float4(0,0,0,0);
            a[1] = mok ? *(const float4*)(Ap + off + 4) : make_float4(0,0,0,0);
            b[0] = bok ? *(const float4*)(Bp + off) : make_float4(0,0,0,0);
            b[1] = bok ? *(const float4*)(Bp + off + 4) : make_float4(0,0,0,0);
        }
#pragma unroll
        for (int k8 = 0; k8 < 4; k8++) {
            int kr = k8 * 8 + t4;
            int mb = wm + g;
            uint32_t ah[4], al[4];
            ah[0] = __float_as_uint(Ah[kr][mb]);
            ah[1] = __float_as_uint(Ah[kr][mb + 8]);
            ah[2] = __float_as_uint(Ah[kr + 4][mb]);
            ah[3] = __float_as_uint(Ah[kr + 4][mb + 8]);
            al[0] = __float_as_uint(Alo[kr][mb]);
            al[1] = __float_as_uint(Alo[kr][mb + 8]);
            al[2] = __float_as_uint(Alo[kr + 4][mb]);
            al[3] = __float_as_uint(Alo[kr + 4][mb + 8]);
#pragma unroll
            for (int ni = 0; ni < 3; ni++) {
                int nb = wn + ni * 8 + g;
                uint32_t b0h = __float_as_uint(Bh[kr][nb]);
                uint32_t b1h = __float_as_uint(Bh[kr + 4][nb]);
                uint32_t b0l = __float_as_uint(Blo[kr][nb]);
                uint32_t b1l = __float_as_uint(Blo[kr + 4][nb]);
                mma_tf32(acc[ni], al, b0h, b1h);
                mma_tf32(acc[ni], ah, b0l, b1l);
                mma_tf32(acc[ni], ah, b0h, b1h);
            }
        }
        __syncthreads();
    }
#pragma unroll
    for (int ni = 0; ni < 3; ni++) {
        int row = m0 + wm + g;
        int col = wn + ni * 8 + 2 * t4;
        if (row < BLT) {
            atomicAdd(&C[(size_t)row * DBCW + col], acc[ni][0]);
            atomicAdd(&C[(size_t)row * DBCW + col + 1], acc[ni][1]);
        }
        if (row + 8 < BLT) {
            atomicAdd(&C[(size_t)(row + 8) * DBCW + col], acc[ni][2]);
            atomicAdd(&C[(size_t)(row + 8) * DBCW + col + 1], acc[ni][3]);
        }
    }
}

// ---------- combine: y = 0.25 * (g0 + rev(g1) + cross(g2) + revcross(g3)) ---
__global__ __launch_bounds__(512)
void combine_k() {
    int bl = blockIdx.x;
    int b = bl / LSEQ, l = bl % LSEQ;
    int e = threadIdx.x;
    size_t r1 = (size_t)(b * LSEQ + (LSEQ - 1 - l)) * EDI;
    size_t r2 = (size_t)(b * LSEQ + pi_map(l)) * EDI;
    size_t r3 = (size_t)(b * LSEQ + pi_map(LSEQ - 1 - l)) * EDI;
    g_y[(size_t)bl * EDI + e] = 0.25f * (g_g[0][(size_t)bl * EDI + e]
                                       + g_g[1][r1 + e]
                                       + g_g[2][r2 + e]
                                       + g_g[3][r3 + e]);
}

// ====== out-GEMM (3xtf32): y @ out_w^T. 64x64, split-K(2), atomic ===========
__global__ __launch_bounds__(256)
void out_gemm_mma(const float* __restrict__ out_w, float* __restrict__ C) {
    __shared__ float Ah[32][72], Alo[32][72];
    __shared__ float Bh[32][72], Blo[32][72];
    int tid = threadIdx.x;
    int n0 = blockIdx.x * 64, m0 = blockIdx.y * 64;
    int kz = blockIdx.z;
    int kbase = kz * 256;
    int ra = tid >> 2, ka = (tid & 3) * 8;
    bool mok = (m0 + ra) < BLT;
    const float* Ap = g_y + (size_t)(m0 + ra) * EDI + kbase + ka;
    const float* Bp = out_w + (size_t)(n0 + ra) * EDI + kbase + ka;
    int lane = tid & 31, wid = tid >> 5;
    int g = lane >> 2, t4 = lane & 3;
    int wm = (wid & 3) * 16, wn = (wid >> 2) * 32;

    float4 a[2], b[2];
    a[0] = mok ? *(const float4*)Ap : make_float4(0,0,0,0);
    a[1] = mok ? *(const float4*)(Ap + 4) : make_float4(0,0,0,0);
    b[0] = *(const float4*)Bp; b[1] = *(const float4*)(Bp + 4);

    float acc[4][4];
#pragma unroll
    for (int ni = 0; ni < 4; ni++)
#pragma unroll
        for (int q = 0; q < 4; q++) acc[ni][q] = 0.f;

#pragma unroll 1
    for (int s2 = 0; s2 < 8; s2++) {
        ST4S(Ah, Alo, ka, ra, a[0]); ST4S(Ah, Alo, ka + 4, ra, a[1]);
        ST4S(Bh, Blo, ka, ra, b[0]); ST4S(Bh, Blo, ka + 4, ra, b[1]);
        __syncthreads();
        if (s2 + 1 < 8) {
            int off = 32 * (s2 + 1);
            a[0] = mok ? *(const float4*)(Ap + off) : make_float4(0,0,0,0);
            a[1] = mok ? *(const float4*)(Ap + off + 4) : make_float4(0,0,0,0);
            b[0] = *(const float4*)(Bp + off); b[1] = *(const float4*)(Bp + off + 4);
        }
#pragma unroll
        for (int k8 = 0; k8 < 4; k8++) {
            int kr = k8 * 8 + t4;
            int mb = wm + g;
            uint32_t ah[4], al[4];
            ah[0] = __float_as_uint(Ah[kr][mb]);
            ah[1] = __float_as_uint(Ah[kr][mb + 8]);
            ah[2] = __float_as_uint(Ah[kr + 4][mb]);
            ah[3] = __float_as_uint(Ah[kr + 4][mb + 8]);
            al[0] = __float_as_uint(Alo[kr][mb]);
            al[1] = __float_as_uint(Alo[kr][mb + 8]);
            al[2] = __float_as_uint(Alo[kr + 4][mb]);
            al[3] = __float_as_uint(Alo[kr + 4][mb + 8]);
#pragma unroll
            for (int ni = 0; ni < 4; ni++) {
                int nb = wn + ni * 8 + g;
                uint32_t b0h = __float_as_uint(Bh[kr][nb]);
                uint32_t b1h = __float_as_uint(Bh[kr + 4][nb]);
                uint32_t b0l = __float_as_uint(Blo[kr][nb]);
                uint32_t b1l = __float_as_uint(Blo[kr + 4][nb]);
                mma_tf32(acc[ni], al, b0h, b1h);
                mma_tf32(acc[ni], ah, b0l, b1l);
                mma_tf32(acc[ni], ah, b0h, b1h);
            }
        }
        __syncthreads();
    }
#pragma unroll
    for (int ni = 0; ni < 4; ni++) {
        int row = m0 + wm + g;
        int col = n0 + wn + ni * 8 + 2 * t4;
        if (row < BLT) {
            atomicAdd(&C[(size_t)row * DMO + col], acc[ni][0]);
            atomicAdd(&C[(size_t)row * DMO + col + 1], acc[ni][1]);
        }
        if (row + 8 < BLT) {
            atomicAdd(&C[(size_t)(row + 8) * DMO + col], acc[ni][2]);
            atomicAdd(&C[(size_t)(row + 8) * DMO + col + 1], acc[ni][3]);
        }
    }
}

// ------------------------- structure check for A = -(n+1) -------------------
__global__ void flag_kernel(AllPtrs P) {
    __shared__ int ok;
    int s = blockIdx.x;
    if (threadIdx.x == 0) ok = 1;
    __syncthreads();
    const float* Al = P.br[s].Al;
    int e = threadIdx.x;
    bool good = true;
#pragma unroll
    for (int n = 0; n < NS; n++) {
        float ref = logf((float)(n + 1));
        if (fabsf(Al[e * NS + n] - ref) > 1e-5f * fmaxf(1.f, fabsf(ref))) good = false;
    }
    if (!good) atomicAnd(&ok, 0);
    __syncthreads();
    if (threadIdx.x == 0) g_fast[s] = ok;
}

// ------- depthwise conv (K=4 causal) + SiLU, rolling window over 6 pos ------
#define CONV_T 6
__global__ __launch_bounds__(512)
void conv_silu(AllPtrs P) {
    int blk = blockIdx.x;
    int ntile = LSEQ / CONV_T;           // 171
    int s  = blk / (BB * ntile);
    int rm = blk % (BB * ntile);
    int b  = rm / ntile;
    int l0 = (rm % ntile) * CONV_T;
    int e  = threadIdx.x;
    float4 cwv = *(const float4*)(P.br[s].cw + e * 4);
    float cb = P.br[s].cb[e];
    float v0 = 0.f, v1 = 0.f, v2 = 0.f;
    if (l0 - 3 >= 0) v0 = g_xz[(size_t)(b * LSEQ + in_row(s, l0 - 3)) * ED2 + e];
    if (l0 - 2 >= 0) v1 = g_xz[(size_t)(b * LSEQ + in_row(s, l0 - 2)) * ED2 + e];
    if (l0 - 1 >= 0) v2 = g_xz[(size_t)(b * LSEQ + in_row(s, l0 - 1)) * ED2 + e];
#pragma unroll
    for (int t = 0; t < CONV_T; t++) {
        int l = l0 + t;
        float v3 = g_xz[(size_t)(b * LSEQ + in_row(s, l)) * ED2 + e];
        float acc = cb;
        acc = fmaf(cwv.x, v0, acc);
        acc = fmaf(cwv.y, v1, acc);
        acc = fmaf(cwv.z, v2, acc);
        acc = fmaf(cwv.w, v3, acc);
        float sg = 1.f / (1.f + __expf(-acc));
        g_xa[s][(size_t)(b * LSEQ + l) * EDI + e] = acc * sg;
        v0 = v1; v1 = v2; v2 = v3;
    }
}

// -------- scan phase 1: chunk summaries, delta fused, channel-quarter -------
__global__ __launch_bounds__(128)
void scan1(AllPtrs P) {
    __shared__ float dtw_s[EQ * 17];
    __shared__ float f_s[CLEN][NS];
    __shared__ float Bsm[CLEN * NS];
    int blk = blockIdx.x;
    int quarter = blk & 3;
    int blk2 = blk >> 2;
    int s = blk2 / (BB * NCHK);
    int rem = blk2 % (BB * NCHK);
    int b = rem / NCHK, c = rem % NCHK;
    int e0 = quarter * EQ;
    int e = e0 + threadIdx.x;
    const float* dtw = P.br[s].dtw;
    for (int idx = threadIdx.x; idx < EQ * RRW; idx += blockDim.x)
        dtw_s[(idx >> 4) * 17 + (idx & 15)] = dtw[e0 * RRW + idx];
    for (int idx = threadIdx.x; idx < CLEN * 32; idx += blockDim.x) {
        int t = idx >> 5, q = idx & 31;
        float v = g_dbc[s][(size_t)(b * LSEQ + c * CLEN + t) * DBCW + q];
        if (q < 16) f_s[t][q] = v;
        else        Bsm[t * NS + (q - 16)] = v;
    }
    __syncthreads();
    float w[RRW];
#pragma unroll
    for (int q = 0; q < RRW; q++) w[q] = dtw_s[threadIdx.x * 17 + q];
    float dtb = P.br[s].dtb[e];
    int fast = g_fast[s];
    float A_[NS];
    if (!fast) {
        const float* Al = P.br[s].Al;
#pragma unroll
        for (int n = 0; n < NS; n++) A_[n] = -__expf(Al[e * NS + n]);
    }
    float h[NS], Pn[NS];
#pragma unroll
    for (int n = 0; n < NS; n++) { h[n] = 0.f; Pn[n] = 1.f; }
    float Rp = 1.f;
    const float* xptr = g_xa[s] + (size_t)(b * LSEQ + c * CLEN) * EDI + e;
    float x_cur = xptr[0];
    for (int t = 0; t < CLEN; t++) {
        float x_nxt = (t + 1 < CLEN) ? xptr[(size_t)(t + 1) * EDI] : 0.f;
        float u = dtb;
#pragma unroll
        for (int q = 0; q < RRW; q++) u = fmaf(f_s[t][q], w[q], u);
        float d = fmaxf(u, 0.f) + log1pf(__expf(-fabsf(u)));
        float dx = d * x_cur;
        if (fast) {
            float r = __expf(-d);
            Rp *= r;
            float dA = 1.f;
#pragma unroll
            for (int n = 0; n < NS; n++) {
                dA *= r;
                h[n] = fmaf(dA, h[n], dx * Bsm[t * NS + n]);
            }
        } else {
#pragma unroll
            for (int n = 0; n < NS; n++) {
                float dA = __expf(d * A_[n]);
                Pn[n] *= dA;
                h[n] = fmaf(dA, h[n], dx * Bsm[t * NS + n]);
            }
        }
        x_cur = x_nxt;
    }
    if (fast) {
        float q = 1.f;
#pragma unroll
        for (int n = 0; n < NS; n++) { q *= Rp; Pn[n] = q; }
    }
    size_t base = (size_t)((s * BB + b) * NCHK + c) * 32 * EDI + e;
#pragma unroll
    for (int n = 0; n < NS; n++) g_sum[base + (size_t)n * EDI] = h[n];
#pragma unroll
    for (int n = 0; n < NS; n++) g_sum[base + (size_t)(16 + n) * EDI] = Pn[n];
}

// ---------- scan phase 2: chunk combine, all loads prefetched ---------------
__global__ __launch_bounds__(512)
void scan2() {
    int n = blockIdx.x & 15;
    int sb = blockIdx.x >> 4;          // s*BB+b
    int e = threadIdx.x;
    float hl[NCHK], Pv[NCHK];
#pragma unroll
    for (int c = 0; c < NCHK; c++) {
        size_t pb = (size_t)(sb * NCHK + c) * 32 * EDI + e;
        hl[c] = g_sum[pb + (size_t)n * EDI];
        Pv[c] = g_sum[pb + (size_t)(16 + n) * EDI];
    }
    float h = 0.f;
#pragma unroll
    for (int c = 0; c < NCHK; c++) {
        g_h0[(size_t)(sb * NCHK + c) * NS * EDI + (size_t)n * EDI + e] = h;
        h = fmaf(Pv[c], h, hl[c]);
    }
}

// -------- scan phase 3: full walk + gate, delta fused, channel-quarter ------
__global__ __launch_bounds__(128)
void scan3(AllPtrs P) {
    __shared__ float dtw_s[EQ * 17];
    __shared__ float f_s[CLEN][NS];
    __shared__ float Bsm[CLEN * NS];
    __shared__ float Csm[CLEN * NS];
    int blk = blockIdx.x;
    int quarter = blk & 3;
    int blk2 = blk >> 2;
    int s = blk2 / (BB * NCHK);
    int rem = blk2 % (BB * NCHK);
    int b = rem / NCHK, c = rem % NCHK;
    int e0 = quarter * EQ;
    int e = e0 + threadIdx.x;
    const float* dtw = P.br[s].dtw;
    for (int idx = threadIdx.x; idx < EQ * RRW; idx += blockDim.x)
        dtw_s[(idx >> 4) * 17 + (idx & 15)] = dtw[e0 * RRW + idx];
    for (int idx = threadIdx.x; idx < CLEN * DBCW; idx += blockDim.x) {
        int t = idx / DBCW, q = idx % DBCW;
        float v = g_dbc[s][(size_t)(b * LSEQ + c * CLEN + t) * DBCW + q];
        if (q < 16)      f_s[t][q] = v;
        else if (q < 32) Bsm[t * NS + (q - 16)] = v;
        else             Csm[t * NS + (q - 32)] = v;
    }
    __syncthreads();
    float w[RRW];
#pragma unroll
    for (int q = 0; q < RRW; q++) w[q] = dtw_s[threadIdx.x * 17 + q];
    float dtb = P.br[s].dtb[e];
    int fast = g_fast[s];
    float A_[NS];
    if (!fast) {
        const float* Al = P.br[s].Al;
#pragma unroll
        for (int n = 0; n < NS; n++) A_[n] = -__expf(Al[e * NS + n]);
    }
    float Dv = P.br[s].Dp[e];
    float h[NS];
    {
        size_t sb = (size_t)((s * BB + b) * NCHK + c);
        size_t hb = sb * NS * EDI + e;
#pragma unroll
        for (int n = 0; n < NS; n++) h[n] = g_h0[hb + (size_t)n * EDI];
    }
    const float* xptr = g_xa[s] + (size_t)(b * LSEQ + c * CLEN) * EDI + e;
    float x_cur = xptr[0];
    float za_cur = g_xz[(size_t)(b * LSEQ + in_row(s, c * CLEN)) * ED2 + EDI + e];
    for (int t = 0; t < CLEN; t++) {
        int l = c * CLEN + t;
        int bl = b * LSEQ + l;
        float x_nxt = 0.f, za_nxt = 0.f;
        if (t + 1 < CLEN) {
            x_nxt = xptr[(size_t)(t + 1) * EDI];
            za_nxt = g_xz[(size_t)(b * LSEQ + in_row(s, l + 1)) * ED2 + EDI + e];
        }
        float u = dtb;
#pragma unroll
        for (int q = 0; q < RRW; q++) u = fmaf(f_s[t][q], w[q], u);
        float d = fmaxf(u, 0.f) + log1pf(__expf(-fabsf(u)));
        float dx = d * x_cur;
        float acc = Dv * x_cur;
        if (fast) {
            float r = __expf(-d);
            float dA = 1.f;
#pragma unroll
            for (int n = 0; n < NS; n++) {
                dA *= r;
                h[n] = fmaf(dA, h[n], dx * Bsm[t * NS + n]);
                acc = fmaf(h[n], Csm[t * NS + n], acc);
            }
        } else {
#pragma unroll
            for (int n = 0; n < NS; n++) {
                float dA = __expf(d * A_[n]);
                h[n] = fmaf(dA, h[n], dx * Bsm[t * NS + n]);
                acc = fmaf(h[n], Csm[t * NS + n], acc);
            }
        }
        float sz = za_cur / (1.f + __expf(-za_cur));
        g_g[s][(size_t)bl * EDI + e] = acc * sz;
        x_cur = x_nxt; za_cur = za_nxt;
    }
}

// ------------------------- launch ------------------------------------------
extern "C" void kernel_launch(void* const* d_in, const int* in_sizes, int n_in,
                              void* d_out, int out_size) {
    const float* x     = (const float*)d_in[0];
    const float* in_w  = (const float*)d_in[1];
    const float* out_w = (const float*)d_in[2];
    AllPtrs P;
    for (int s = 0; s < NBR; s++) {
        int o = 3 + 7 * s;
        P.br[s].cw  = (const float*)d_in[o + 0];
        P.br[s].cb  = (const float*)d_in[o + 1];
        P.br[s].xpw = (const float*)d_in[o + 2];
        P.br[s].dtw = (const float*)d_in[o + 3];
        P.br[s].dtb = (const float*)d_in[o + 4];
        P.br[s].Al  = (const float*)d_in[o + 5];
        P.br[s].Dp  = (const float*)d_in[o + 6];
    }
    float *p_xz, *p_dbc;
    cudaGetSymbolAddress((void**)&p_xz,  g_xz);
    cudaGetSymbolAddress((void**)&p_dbc, g_dbc);

    const int IN_SMEM = (2*32*136 + 2*32*72) * 4;  // 53248 bytes
    cudaFuncSetAttribute(in_gemm_mma, cudaFuncAttributeMaxDynamicSharedMemorySize, IN_SMEM);

    flag_kernel<<<NBR, EDI>>>(P);

    // xz = x @ in_w^T : [2052,1024], K=256 — 3xtf32, 272 blocks
    in_gemm_mma<<<dim3(ED2 / 64, (BLT + 127) / 128), 256, IN_SMEM>>>(x, in_w, p_xz);

    // per-branch permuted depthwise conv + SiLU — 1368 blocks
    conv_silu<<<NBR * BB * (LSEQ / CONV_T), 512>>>(P);

    // dBC = xa @ xp_w^T : split-K(2), 264 blocks, atomic accumulate
    cudaMemsetAsync(p_dbc, 0, (size_t)NBR * BLT * DBCW * sizeof(float));
    dbc_mma<<<dim3(NBR, (BLT + 63) / 64, 2), 256>>>(P);

    // chunked selective scan — 576 / 128 (prefetched) / 576 blocks
    scan1<<<NBR * BB * NCHK * 4, 128>>>(P);
    scan2<<<NBR * BB * NS, EDI>>>();
    scan3<<<NBR * BB * NCHK * 4, 128>>>(P);

    // combine permuted branch outputs into y — 2052 blocks
    combine_k<<<BLT, EDI>>>();

    // out = y @ out_w^T : split-K(2), 264 blocks, atomic accumulate
    cudaMemsetAsync(d_out, 0, (size_t)BLT * DMO * sizeof(float));
    out_gemm_mma<<<dim3(DMO / 64, (BLT + 63) / 64, 2), 256>>>(out_w, (float*)d_out);
}